// round 7
// baseline (speedup 1.0000x reference)
#include <cuda_runtime.h>
#include <cuda_bf16.h>
#include <stdint.h>
#include <math.h>

typedef unsigned int u32;

// ---------------- problem constants ----------------
#define BB 8
#define TT 1024
#define CIN 55
#define DD 512
#define LL 3
#define SEQW 10
#define TRR 512          // masked count
#define TU 512           // unmasked count (T - TR)

// ---------------- fp32 scratch ----------------
__device__ float g_pe[TT * DD];
__device__ float g_ex[BB * TT * DD];
__device__ float g_xe[BB * TU * DD];
__device__ float g_v [BB * TT * DD];
__device__ float g_att[BB * TU * TU];     // encoder attention scratch
__device__ float g_t1[BB * TT * DD];
__device__ float g_tok[BB * TT * DD];
__device__ float g_score[BB * TT];
__device__ int   g_flag[BB * TT];
__device__ int   g_upos[BB * TT];
__device__ int   g_ulist[BB * TU];

// ---------------- bf16 hi/lo scratch ----------------
#define NXE (BB * TT * DD)
__device__ __nv_bfloat16 g_XH[NXE], g_XL[NXE];        // layer input hi/lo
__device__ __nv_bfloat16 g_QH[NXE], g_QL[NXE];        // q (also gelu out)
__device__ __nv_bfloat16 g_KH[NXE], g_KL[NXE];        // k
__device__ __nv_bfloat16 g_SH[BB*TT*TT/1], g_SL[BB*TT*TT/1]; // att probs (dec worst case 8M)
__device__ __nv_bfloat16 g_VH[NXE], g_VL[NXE];        // v^T
__device__ __nv_bfloat16 g_TH[NXE], g_TL[NXE];        // ln out
__device__ __nv_bfloat16 g_WH[2048*512], g_WL[2048*512]; // weights (qkv + o)

// ---------------- PE ----------------
__global__ void pe_kernel() {
    int t = blockIdx.x;
    int i = threadIdx.x;                 // 0..255
    float divv = expf((float)(2 * i) * (-9.210340371976184f / (float)DD));
    float ang = (float)t * divv;
    g_pe[t * DD + 2 * i]     = sinf(ang);
    g_pe[t * DD + 2 * i + 1] = cosf(ang);
}

// ---------------- embedding: circular conv1d + PE ----------------
__global__ void embed_kernel(const float* __restrict__ x, const float* __restrict__ cw,
                             float* __restrict__ ex) {
    int t = blockIdx.x, b = blockIdx.y;
    __shared__ float sw[CIN * 3];
    int tid = threadIdx.x;               // 128 threads
    for (int i = tid; i < CIN * 3; i += 128) {
        int c = i / 3, k = i % 3;
        int tt = t + k - 1;
        if (tt < 0) tt += TT;
        if (tt >= TT) tt -= TT;
        sw[i] = x[((long long)b * TT + tt) * CIN + c];
    }
    __syncthreads();
#pragma unroll
    for (int p = 0; p < 4; p++) {
        int d = tid + p * 128;
        const float* w = cw + (long long)d * (CIN * 3);
        float acc = 0.f;
#pragma unroll 15
        for (int i = 0; i < CIN * 3; i++) acc = fmaf(sw[i], w[i], acc);
        ex[((long long)b * TT + t) * DD + d] = acc + g_pe[t * DD + d];
    }
}

// ---------------- windowed mean/var score ----------------
__global__ void score_kernel(const float* __restrict__ ex, float* __restrict__ score) {
    int t = blockIdx.x, b = blockIdx.y;
    int lo = t - (SEQW - 1); if (lo < 0) lo = 0;
    float inv = 1.f / (float)(t + 1 - lo);
    int tid = threadIdx.x;               // 256
    float vs = 0.f, ms = 0.f;
#pragma unroll
    for (int p = 0; p < 2; p++) {
        int d = tid + p * 256;
        float s1 = 0.f, s2 = 0.f;
        for (int w = lo; w <= t; w++) {
            float v = ex[((long long)b * TT + w) * DD + d];
            s1 += v; s2 += v * v;
        }
        float m = s1 * inv, m2 = s2 * inv;
        vs += m2 - m * m;
        ms += m;
    }
    __shared__ float rv[256], rm[256];
    rv[tid] = vs; rm[tid] = ms; __syncthreads();
    for (int s = 128; s > 0; s >>= 1) {
        if (tid < s) { rv[tid] += rv[tid + s]; rm[tid] += rm[tid + s]; }
        __syncthreads();
    }
    if (tid == 0) score[b * TT + t] = rv[0] / rm[0];
}

// ---------------- selection: rank with top_k tie-break ----------------
__global__ void select_kernel() {
    int b = blockIdx.x;
    int t = threadIdx.x;                 // 1024 threads
    __shared__ float ss[TT];
    __shared__ int   sf[TT];
    float myv = g_score[b * TT + t];
    ss[t] = myv;
    __syncthreads();
    int rank = 0;
    for (int i = 0; i < TT; i++) {
        float o = ss[i];
        rank += (o > myv) || (o == myv && i < t);
    }
    int masked = (rank < TRR) ? 1 : 0;
    sf[t] = masked;
    __syncthreads();
    int ucnt = 0;
    for (int i = 0; i < t; i++) ucnt += (sf[i] == 0);
    g_flag[b * TT + t] = masked;
    if (!masked) {
        g_upos[b * TT + t] = ucnt;
        g_ulist[b * TU + ucnt] = t;
    } else {
        g_upos[b * TT + t] = -1;
    }
}

// ---------------- split helper ----------------
__device__ __forceinline__ void writeHL2(__nv_bfloat16* H, __nv_bfloat16* L,
                                         long long idx, float v0, float v1) {
    __nv_bfloat16 h0 = __float2bfloat16(v0), h1 = __float2bfloat16(v1);
    __nv_bfloat162 hh = __halves2bfloat162(h0, h1);
    __nv_bfloat162 ll = __floats2bfloat162_rn(v0 - __bfloat162float(h0),
                                              v1 - __bfloat162float(h1));
    *(__nv_bfloat162*)(H + idx) = hh;
    *(__nv_bfloat162*)(L + idx) = ll;
}
__device__ __forceinline__ void writeHL1(__nv_bfloat16* H, __nv_bfloat16* L,
                                         long long idx, float v) {
    __nv_bfloat16 h = __float2bfloat16(v);
    H[idx] = h;
    L[idx] = __float2bfloat16(v - __bfloat162float(h));
}

// ---------------- gather unmasked tokens (+ hi/lo) ----------------
__global__ void gather_kernel(const float* __restrict__ ex, float* __restrict__ xe,
                              __nv_bfloat16* __restrict__ XH, __nv_bfloat16* __restrict__ XL) {
    int p = blockIdx.x, b = blockIdx.y;
    int t = g_ulist[b * TU + p];
    const float* src = ex + ((long long)b * TT + t) * DD;
    long long o = ((long long)b * TU + p) * DD;
    for (int d = threadIdx.x; d < DD; d += 256) {
        float v = src[d];
        xe[o + d] = v;
        writeHL1(XH, XL, o + d, v);
    }
}

// ---------------- build decoder tokens (+ hi/lo) ----------------
__global__ void tokens_kernel(const float* __restrict__ ux, const float* __restrict__ mtk,
                              float* __restrict__ tok,
                              __nv_bfloat16* __restrict__ XH, __nv_bfloat16* __restrict__ XL) {
    int t = blockIdx.x, b = blockIdx.y;
    long long o = ((long long)b * TT + t) * DD;
    if (g_flag[b * TT + t]) {
        for (int d = threadIdx.x; d < DD; d += 256) {
            float v = mtk[d] + g_pe[t * DD + d];
            tok[o + d] = v;
            writeHL1(XH, XL, o + d, v);
        }
    } else {
        int p = g_upos[b * TT + t];
        const float* src = ux + ((long long)b * TU + p) * DD;
        for (int d = threadIdx.x; d < DD; d += 256) {
            float v = src[d];
            tok[o + d] = v;
            writeHL1(XH, XL, o + d, v);
        }
    }
}

// ---------------- transpose-split: X [b][R][C] fp32 -> H,L [b][C][R] bf16 ----------------
__global__ void tsplit_kernel(const float* __restrict__ X, __nv_bfloat16* __restrict__ H,
                              __nv_bfloat16* __restrict__ L, int R, int C) {
    __shared__ float tile[32][33];
    int b = blockIdx.z;
    int c0 = blockIdx.x * 32, r0 = blockIdx.y * 32;
    const float* Xb = X + (long long)b * R * C;
    int tx = threadIdx.x, ty = threadIdx.y;   // 32 x 8
#pragma unroll
    for (int i = ty; i < 32; i += 8)
        tile[i][tx] = Xb[(long long)(r0 + i) * C + c0 + tx];
    __syncthreads();
    long long ob = (long long)b * C * R;
#pragma unroll
    for (int i = ty; i < 32; i += 8) {
        float v = tile[tx][i];
        writeHL1(H, L, ob + (long long)(c0 + i) * R + r0 + tx, v);
    }
}

// ================= tensor-core GEMM on pre-split bf16 =================
// modes: 0: C=alpha*acc(+bias)(+resid)            (batched ok)
//        1: gelu -> C    2: sigmoid -> C
//        3: hi/lo -> Oh/Ol
//        4: C fp32 AND hi/lo -> Oh/Ol
//        5: QKV merged: n<512 -> Oh/Ol (+bias), n<1024 -> Oh2/Ol2 (+bias2),
//           else -> C fp32 (+bias3); all outputs row stride 512
//        6: gelu -> hi/lo Oh/Ol

#define RSTR 40   // halfwords per smem row (32 data + 8 pad)
#define PARTB (128 * RSTR * 2)
#define STAGEB (4 * PARTB)
#define NSTAGE 3

__device__ __forceinline__ void cpa(u32 dst, const void* src) {
    asm volatile("cp.async.cg.shared.global [%0], [%1], 16;\n" :: "r"(dst), "l"(src));
}
__device__ __forceinline__ void ldsm4(u32* r, u32 addr) {
    asm volatile("ldmatrix.sync.aligned.m8n8.x4.shared.b16 {%0,%1,%2,%3}, [%4];\n"
        : "=r"(r[0]), "=r"(r[1]), "=r"(r[2]), "=r"(r[3]) : "r"(addr));
}
__device__ __forceinline__ void mma16816(float* d, const u32* a, u32 b0, u32 b1) {
    asm volatile(
        "mma.sync.aligned.m16n8k16.row.col.f32.bf16.bf16.f32 "
        "{%0,%1,%2,%3}, {%4,%5,%6,%7}, {%8,%9}, {%0,%1,%2,%3};\n"
        : "+f"(d[0]), "+f"(d[1]), "+f"(d[2]), "+f"(d[3])
        : "r"(a[0]), "r"(a[1]), "r"(a[2]), "r"(a[3]), "r"(b0), "r"(b1));
}

__device__ __forceinline__ void load_stage(
    u32 sbase, const __nv_bfloat16* Ah, const __nv_bfloat16* Al,
    const __nv_bfloat16* Bh, const __nv_bfloat16* Bl,
    int m0, int n0, int K, int k0, int tid) {
    int r = tid >> 2, c = tid & 3;
    u32 off1 = (u32)(r * RSTR + c * 8) * 2;
    u32 off2 = (u32)((r + 64) * RSTR + c * 8) * 2;
    long long a1 = (long long)(m0 + r) * K + k0 + c * 8;
    long long a2 = a1 + (long long)64 * K;
    long long b1 = (long long)(n0 + r) * K + k0 + c * 8;
    long long b2 = b1 + (long long)64 * K;
    cpa(sbase + off1, Ah + a1);               cpa(sbase + off2, Ah + a2);
    cpa(sbase + PARTB + off1, Al + a1);       cpa(sbase + PARTB + off2, Al + a2);
    cpa(sbase + 2*PARTB + off1, Bh + b1);     cpa(sbase + 2*PARTB + off2, Bh + b2);
    cpa(sbase + 3*PARTB + off1, Bl + b1);     cpa(sbase + 3*PARTB + off2, Bl + b2);
    asm volatile("cp.async.commit_group;\n");
}

__global__ __launch_bounds__(256)
void gemm3_kernel(const __nv_bfloat16* __restrict__ Ah, const __nv_bfloat16* __restrict__ Al,
                  const __nv_bfloat16* __restrict__ Bh, const __nv_bfloat16* __restrict__ Bl,
                  const float* __restrict__ bias, const float* __restrict__ bias2,
                  const float* __restrict__ bias3,
                  const float* __restrict__ resid, float* __restrict__ C,
                  __nv_bfloat16* __restrict__ Oh, __nv_bfloat16* __restrict__ Ol,
                  __nv_bfloat16* __restrict__ Oh2, __nv_bfloat16* __restrict__ Ol2,
                  int M, int N, int K,
                  long long sA, long long sB, long long sC,
                  float alpha, int mode) {
    extern __shared__ __nv_bfloat16 smraw[];
    u32 smb = (u32)__cvta_generic_to_shared(smraw);

    int bz = blockIdx.z;
    Ah += (long long)bz * sA; Al += (long long)bz * sA;
    Bh += (long long)bz * sB; Bl += (long long)bz * sB;
    C  += (long long)bz * sC;
    const float* R = resid ? resid + (long long)bz * sC : nullptr;

    int m0 = blockIdx.y * 128, n0 = blockIdx.x * 128;
    int tid = threadIdx.x, lane = tid & 31, wid = tid >> 5;
    int wm = (wid & 1) * 64, wn = (wid >> 1) * 32;
    int g = lane >> 2, t4 = lane & 3;

    float acc[4][4][4];
#pragma unroll
    for (int i = 0; i < 4; i++)
#pragma unroll
        for (int j = 0; j < 4; j++)
#pragma unroll
            for (int q = 0; q < 4; q++) acc[i][j][q] = 0.f;

    int nk = K / 32;
    load_stage(smb, Ah, Al, Bh, Bl, m0, n0, K, 0, tid);
    load_stage(smb + STAGEB, Ah, Al, Bh, Bl, m0, n0, K, 32, tid);

    int arow = lane & 15;
    int achkbase = lane >> 4;
    int brow = (lane & 7) + ((lane & 16) >> 1);
    int bchkbase = (lane >> 3) & 1;

    int buf = 0;
    for (int kt = 0; kt < nk; kt++) {
        asm volatile("cp.async.wait_group 1;\n");
        __syncthreads();
        // prefetch kt+2 into buffer (buf+2)%3 (safe: last read at iter kt-1, all
        // warps passed this iteration's sync)
        if (kt + 2 < nk) {
            int nb = buf + 2; if (nb >= NSTAGE) nb -= NSTAGE;
            load_stage(smb + nb * STAGEB, Ah, Al, Bh, Bl, m0, n0, K, (kt + 2) * 32, tid);
        } else {
            asm volatile("cp.async.commit_group;\n");
        }
        u32 base = smb + buf * STAGEB;
        u32 aH = base, aL = base + PARTB, bH = base + 2*PARTB, bL = base + 3*PARTB;
#pragma unroll
        for (int kq = 0; kq < 2; kq++) {
            u32 ah[4][4], al[4][4];
            int achk = kq * 2 + achkbase;
#pragma unroll
            for (int mf = 0; mf < 4; mf++) {
                u32 off = (u32)((wm + mf * 16 + arow) * RSTR + achk * 8) * 2;
                ldsm4(ah[mf], aH + off);
                ldsm4(al[mf], aL + off);
            }
            int bchk = kq * 2 + bchkbase;
#pragma unroll
            for (int np = 0; np < 2; np++) {
                u32 off = (u32)((wn + np * 16 + brow) * RSTR + bchk * 8) * 2;
                u32 bh[4], bl[4];
                ldsm4(bh, bH + off);
                ldsm4(bl, bL + off);
#pragma unroll
                for (int ni = 0; ni < 2; ni++) {
                    int nf = np * 2 + ni;
                    u32 b0h = bh[ni*2], b1h = bh[ni*2+1];
                    u32 b0l = bl[ni*2], b1l = bl[ni*2+1];
#pragma unroll
                    for (int mf = 0; mf < 4; mf++) {
                        mma16816(acc[mf][nf], ah[mf], b0h, b1h);
                        mma16816(acc[mf][nf], ah[mf], b0l, b1l);
                        mma16816(acc[mf][nf], al[mf], b0h, b1h);
                    }
                }
            }
        }
        buf++; if (buf >= NSTAGE) buf = 0;
    }

    // ---- epilogue ----
#pragma unroll
    for (int mf = 0; mf < 4; mf++) {
        int r0 = m0 + wm + mf * 16 + g;
#pragma unroll
        for (int nf = 0; nf < 4; nf++) {
            int cc = n0 + wn + nf * 8 + t4 * 2;
#pragma unroll
            for (int half = 0; half < 2; half++) {
                int r = r0 + half * 8;
                float v0 = acc[mf][nf][half * 2 + 0] * alpha;
                float v1 = acc[mf][nf][half * 2 + 1] * alpha;
                if (mode == 5) {
                    int reg = cc >> 9, lc = cc & 511;
                    long long idx = (long long)r * 512 + lc;
                    if (reg == 0) {
                        v0 += bias[lc]; v1 += bias[lc + 1];
                        writeHL2(Oh, Ol, idx, v0, v1);
                    } else if (reg == 1) {
                        v0 += bias2[lc]; v1 += bias2[lc + 1];
                        writeHL2(Oh2, Ol2, idx, v0, v1);
                    } else {
                        v0 += bias3[lc]; v1 += bias3[lc + 1];
                        *(float2*)(C + idx) = make_float2(v0, v1);
                    }
                } else {
                    if (bias) { v0 += bias[cc]; v1 += bias[cc + 1]; }
                    if (R) {
                        v0 += R[(long long)r * N + cc];
                        v1 += R[(long long)r * N + cc + 1];
                    }
                    if (mode == 1 || mode == 6) {
                        v0 = 0.5f * v0 * (1.f + erff(v0 * 0.7071067811865475f));
                        v1 = 0.5f * v1 * (1.f + erff(v1 * 0.7071067811865475f));
                    } else if (mode == 2) {
                        v0 = 1.f / (1.f + __expf(-v0));
                        v1 = 1.f / (1.f + __expf(-v1));
                    }
                    long long idx = (long long)r * N + cc;
                    if (mode <= 2 || mode == 4)
                        *(float2*)(C + idx) = make_float2(v0, v1);
                    if (mode == 3 || mode == 4 || mode == 6)
                        writeHL2(Oh, Ol, idx, v0, v1);
                }
            }
        }
    }
}

// ---------------- softmax over rows (+ hi/lo emit) ----------------
__global__ void softmax_split_kernel(float* __restrict__ S,
                                     __nv_bfloat16* __restrict__ H,
                                     __nv_bfloat16* __restrict__ L, int Nc) {
    long long row = blockIdx.x;
    float* p = S + row * Nc;
    __shared__ float red[256];
    int tid = threadIdx.x;
    float mx = -1e30f;
    for (int i = tid; i < Nc; i += 256) mx = fmaxf(mx, p[i]);
    red[tid] = mx; __syncthreads();
    for (int s = 128; s > 0; s >>= 1) { if (tid < s) red[tid] = fmaxf(red[tid], red[tid + s]); __syncthreads(); }
    mx = red[0]; __syncthreads();
    float sum = 0.f;
    for (int i = tid; i < Nc; i += 256) { float e = __expf(p[i] - mx); p[i] = e; sum += e; }
    red[tid] = sum; __syncthreads();
    for (int s = 128; s > 0; s >>= 1) { if (tid < s) red[tid] += red[tid + s]; __syncthreads(); }
    float inv = 1.f / red[0];
    long long ro = row * Nc;
    for (int i = tid; i < Nc; i += 256) {
        float e = p[i] * inv;
        p[i] = e;
        writeHL1(H, L, ro + i, e);
    }
}

// ---------------- layer norm (row 512) -> fp32 ----------------
__global__ void ln_kernel(const float* __restrict__ X, const float* __restrict__ g,
                          const float* __restrict__ b, float* __restrict__ Y) {
    long long row = blockIdx.x;
    const float* x = X + row * DD;
    float* y = Y + row * DD;
    __shared__ float red[256];
    int tid = threadIdx.x;
    float v0 = x[tid], v1 = x[tid + 256];
    red[tid] = v0 + v1; __syncthreads();
    for (int s = 128; s > 0; s >>= 1) { if (tid < s) red[tid] += red[tid + s]; __syncthreads(); }
    float mu = red[0] * (1.f / (float)DD); __syncthreads();
    float d0 = v0 - mu, d1 = v1 - mu;
    red[tid] = d0 * d0 + d1 * d1; __syncthreads();
    for (int s = 128; s > 0; s >>= 1) { if (tid < s) red[tid] += red[tid + s]; __syncthreads(); }
    float inv = rsqrtf(red[0] * (1.f / (float)DD) + 1e-5f);
    y[tid]       = d0 * inv * g[tid] + b[tid];
    y[tid + 256] = d1 * inv * g[tid + 256] + b[tid + 256];
}

// ---------------- layer norm (row 512) -> hi/lo bf16 ----------------
__global__ void ln_split_kernel(const float* __restrict__ X, const float* __restrict__ g,
                                const float* __restrict__ b,
                                __nv_bfloat16* __restrict__ H, __nv_bfloat16* __restrict__ L) {
    long long row = blockIdx.x;
    const float* x = X + row * DD;
    __shared__ float red[256];
    int tid = threadIdx.x;
    float v0 = x[tid], v1 = x[tid + 256];
    red[tid] = v0 + v1; __syncthreads();
    for (int s = 128; s > 0; s >>= 1) { if (tid < s) red[tid] += red[tid + s]; __syncthreads(); }
    float mu = red[0] * (1.f / (float)DD); __syncthreads();
    float d0 = v0 - mu, d1 = v1 - mu;
    red[tid] = d0 * d0 + d1 * d1; __syncthreads();
    for (int s = 128; s > 0; s >>= 1) { if (tid < s) red[tid] += red[tid + s]; __syncthreads(); }
    float inv = rsqrtf(red[0] * (1.f / (float)DD) + 1e-5f);
    long long ro = row * DD;
    writeHL1(H, L, ro + tid,       d0 * inv * g[tid] + b[tid]);
    writeHL1(H, L, ro + tid + 256, d1 * inv * g[tid + 256] + b[tid + 256]);
}

// ---------------- host orchestration ----------------
extern "C" void kernel_launch(void* const* d_in, const int* in_sizes, int n_in,
                              void* d_out, int out_size) {
    float *ex, *xe, *v, *att, *t1, *tok, *score;
    cudaGetSymbolAddress((void**)&ex,  g_ex);
    cudaGetSymbolAddress((void**)&xe,  g_xe);
    cudaGetSymbolAddress((void**)&v,   g_v);
    cudaGetSymbolAddress((void**)&att, g_att);
    cudaGetSymbolAddress((void**)&t1,  g_t1);
    cudaGetSymbolAddress((void**)&tok, g_tok);
    cudaGetSymbolAddress((void**)&score, g_score);
    __nv_bfloat16 *XH,*XL,*QH,*QL,*KH,*KL,*SH,*SL,*VH,*VL,*TH,*TL,*WH,*WL;
    cudaGetSymbolAddress((void**)&XH, g_XH); cudaGetSymbolAddress((void**)&XL, g_XL);
    cudaGetSymbolAddress((void**)&QH, g_QH); cudaGetSymbolAddress((void**)&QL, g_QL);
    cudaGetSymbolAddress((void**)&KH, g_KH); cudaGetSymbolAddress((void**)&KL, g_KL);
    cudaGetSymbolAddress((void**)&SH, g_SH); cudaGetSymbolAddress((void**)&SL, g_SL);
    cudaGetSymbolAddress((void**)&VH, g_VH); cudaGetSymbolAddress((void**)&VL, g_VL);
    cudaGetSymbolAddress((void**)&TH, g_TH); cudaGetSymbolAddress((void**)&TL, g_TL);
    cudaGetSymbolAddress((void**)&WH, g_WH); cudaGetSymbolAddress((void**)&WL, g_WL);

    static int smem_set = 0;
    if (!smem_set) {
        cudaFuncSetAttribute(gemm3_kernel, cudaFuncAttributeMaxDynamicSharedMemorySize,
                             NSTAGE * STAGEB);
        smem_set = 1;
    }

    const float* in[31];
    for (int i = 0; i < 31 && i < n_in; i++) in[i] = (const float*)d_in[i];

    const float *x = in[0], *conv_w = in[1], *mask_token = in[2];
    const float *pro_w1, *pro_b1, *pro_w2, *pro_b2;
    const float *eW[4], *eBi[4], *eg, *ebb, *eng, *enb;
    const float *dW[4], *dBi[4], *dg, *dbb, *dng, *dnb;

    bool sig = (in_sizes[3] == LL * DD * DD);
    if (sig) {
        eW[0]=in[3];  eBi[0]=in[4];  eW[1]=in[5];  eBi[1]=in[6];
        eW[2]=in[7];  eBi[2]=in[8];  eW[3]=in[9];  eBi[3]=in[10];
        eg=in[11]; ebb=in[12]; eng=in[13]; enb=in[14];
        dW[0]=in[15]; dBi[0]=in[16]; dW[1]=in[17]; dBi[1]=in[18];
        dW[2]=in[19]; dBi[2]=in[20]; dW[3]=in[21]; dBi[3]=in[22];
        dg=in[23]; dbb=in[24]; dng=in[25]; dnb=in[26];
        pro_w1=in[27]; pro_b1=in[28]; pro_w2=in[29]; pro_b2=in[30];
    } else {
        pro_w1=in[3]; pro_b1=in[4]; pro_w2=in[5]; pro_b2=in[6];
        eW[0]=in[7];  eW[1]=in[8];  eW[2]=in[9];  eW[3]=in[10];
        eBi[0]=in[11]; eBi[1]=in[12]; eBi[2]=in[13]; eBi[3]=in[14];
        eg=in[15]; ebb=in[16]; eng=in[17]; enb=in[18];
        dW[0]=in[19]; dW[1]=in[20]; dW[2]=in[21]; dW[3]=in[22];
        dBi[0]=in[23]; dBi[1]=in[24]; dBi[2]=in[25]; dBi[3]=in[26];
        dg=in[27]; dbb=in[28]; dng=in[29]; dnb=in[30];
    }

    const float SCALE = 0.044194173824159216f;  // 1/sqrt(512)

    auto tsplit = [&](const float* X, __nv_bfloat16* H, __nv_bfloat16* L, int R, int C, int nb) {
        tsplit_kernel<<<dim3(C / 32, R / 32, nb), dim3(32, 8)>>>(X, H, L, R, C);
    };
    auto gemm = [&](const __nv_bfloat16* ah, const __nv_bfloat16* al,
                    const __nv_bfloat16* bh, const __nv_bfloat16* bl,
                    const float* b1, const float* b2, const float* b3,
                    const float* resid, float* C,
                    __nv_bfloat16* oh, __nv_bfloat16* ol,
                    __nv_bfloat16* oh2, __nv_bfloat16* ol2,
                    int M, int N, int K, long long sA, long long sB, long long sC,
                    int nb, float alpha, int mode) {
        dim3 grid(N / 128, M / 128, nb);
        gemm3_kernel<<<grid, 256, NSTAGE * STAGEB>>>(ah, al, bh, bl, b1, b2, b3, resid, C,
                                                     oh, ol, oh2, ol2,
                                                     M, N, K, sA, sB, sC, alpha, mode);
    };

    // ---- embedding + score + selection ----
    pe_kernel<<<TT, 256>>>();
    embed_kernel<<<dim3(TT, BB), 128>>>(x, conv_w, ex);
    score_kernel<<<dim3(TT, BB), 256>>>(ex, score);
    select_kernel<<<BB, TT>>>();
    gather_kernel<<<dim3(TU, BB), 256>>>(ex, xe, XH, XL);

    // ---- encoder (Tc = 512) ----
    {
        int Tc = TU, BT = BB * Tc;
        long long sQK = (long long)Tc * DD, sAtt = (long long)Tc * Tc;
        for (int l = 0; l < LL; l++) {
            const float *Wq = eW[0] + (long long)l * DD * DD, *bq = eBi[0] + l * DD;
            const float *Wk = eW[1] + (long long)l * DD * DD, *bk = eBi[1] + l * DD;
            const float *Wv = eW[2] + (long long)l * DD * DD, *bv = eBi[2] + l * DD;
            const float *Wo = eW[3] + (long long)l * DD * DD, *bo = eBi[3] + l * DD;
            // weight prep: [N][K] rows q:0-511, k:512-1023, v:1024-1535, o:1536-2047
            tsplit(Wq, WH,             WL,             DD, DD, 1);
            tsplit(Wk, WH + 512*512,   WL + 512*512,   DD, DD, 1);
            tsplit(Wv, WH + 1024*512,  WL + 1024*512,  DD, DD, 1);
            tsplit(Wo, WH + 1536*512,  WL + 1536*512,  DD, DD, 1);
            // merged QKV
            gemm(XH, XL, WH, WL, bq, bk, bv, nullptr, v, QH, QL, KH, KL,
                 BT, 1536, DD, 0, 0, 0, 1, 1.f, 5);
            // QK^T
            gemm(QH, QL, KH, KL, nullptr, nullptr, nullptr, nullptr, att,
                 nullptr, nullptr, nullptr, nullptr,
                 Tc, Tc, DD, sQK, sQK, sAtt, BB, SCALE, 0);
            softmax_split_kernel<<<BB * Tc, 256>>>(att, SH, SL, Tc);
            tsplit(v, VH, VL, Tc, DD, BB);
            // AV + resid(xe)
            gemm(SH, SL, VH, VL, nullptr, nullptr, nullptr, xe, t1,
                 nullptr, nullptr, nullptr, nullptr,
                 Tc, DD, Tc, sAtt, sQK, sQK, BB, 1.f, 0);
            ln_split_kernel<<<BT, 256>>>(t1, eg + l * DD, ebb + l * DD, TH, TL);
            // Wo proj + resid(t1) -> xe fp32 + XH/XL
            gemm(TH, TL, WH + 1536*512, WL + 1536*512, bo, nullptr, nullptr, t1, xe,
                 XH, XL, nullptr, nullptr, BT, DD, DD, 0, 0, 0, 1, 1.f, 4);
        }
        ln_kernel<<<BT, 256>>>(xe, eng, enb, t1);    // ux fp32 in t1
    }

    // ---- decoder tokens ----
    tokens_kernel<<<dim3(TT, BB), 256>>>(t1, mask_token, tok, XH, XL);

    // ---- decoder (Tc = 1024), att maps into d_out ----
    {
        int Tc = TT, BT = BB * Tc;
        long long sQK = (long long)Tc * DD, sAtt = (long long)Tc * Tc;
        for (int l = 0; l < LL; l++) {
            const float *Wq = dW[0] + (long long)l * DD * DD, *bq = dBi[0] + l * DD;
            const float *Wk = dW[1] + (long long)l * DD * DD, *bk = dBi[1] + l * DD;
            const float *Wv = dW[2] + (long long)l * DD * DD, *bv = dBi[2] + l * DD;
            const float *Wo = dW[3] + (long long)l * DD * DD, *bo = dBi[3] + l * DD;
            float* attOut = (float*)d_out + (long long)l * BB * TT * TT;
            tsplit(Wq, WH,             WL,             DD, DD, 1);
            tsplit(Wk, WH + 512*512,   WL + 512*512,   DD, DD, 1);
            tsplit(Wv, WH + 1024*512,  WL + 1024*512,  DD, DD, 1);
            tsplit(Wo, WH + 1536*512,  WL + 1536*512,  DD, DD, 1);
            gemm(XH, XL, WH, WL, bq, bk, bv, nullptr, v, QH, QL, KH, KL,
                 BT, 1536, DD, 0, 0, 0, 1, 1.f, 5);
            gemm(QH, QL, KH, KL, nullptr, nullptr, nullptr, nullptr, attOut,
                 nullptr, nullptr, nullptr, nullptr,
                 Tc, Tc, DD, sQK, sQK, sAtt, BB, SCALE, 0);
            softmax_split_kernel<<<BB * Tc, 256>>>(attOut, SH, SL, Tc);
            tsplit(v, VH, VL, Tc, DD, BB);
            gemm(SH, SL, VH, VL, nullptr, nullptr, nullptr, tok, t1,
                 nullptr, nullptr, nullptr, nullptr,
                 Tc, DD, Tc, sAtt, sQK, sQK, BB, 1.f, 0);
            ln_split_kernel<<<BT, 256>>>(t1, dg + l * DD, dbb + l * DD, TH, TL);
            gemm(TH, TL, WH + 1536*512, WL + 1536*512, bo, nullptr, nullptr, t1, tok,
                 XH, XL, nullptr, nullptr, BT, DD, DD, 0, 0, 0, 1, 1.f, 4);
        }
        ln_split_kernel<<<BT, 256>>>(tok, dng, dnb, TH, TL);   // dx hi/lo

        // ---- projector ----
        float* rec = (float*)d_out + (long long)LL * BB * TT * TT;
        tsplit(pro_w1, WH, WL, DD, DD, 1);
        gemm(TH, TL, WH, WL, pro_b1, nullptr, nullptr, nullptr, nullptr,
             QH, QL, nullptr, nullptr, BT, DD, DD, 0, 0, 0, 1, 1.f, 6);
        tsplit(pro_w2, WH, WL, DD, DD, 1);
        gemm(QH, QL, WH, WL, pro_b2, nullptr, nullptr, nullptr, rec,
             nullptr, nullptr, nullptr, nullptr, BT, DD, DD, 0, 0, 0, 1, 1.f, 2);
    }
}